// round 2
// baseline (speedup 1.0000x reference)
#include <cuda_runtime.h>

// Problem constants
#define NPTS    65536
#define NWIN    512
#define NH      8
#define DHH     64
#define POSBND  15
#define RPE_ROWS 93          // 3 * (2*15+1)
#define SCALEQ  0.125f       // 64^-0.5

typedef unsigned long long ull;

// Scratch (device globals; no allocation APIs allowed)
__device__ float g_qkv[100663296];   // [N][1536] in gathered (serialized) order
__device__ float g_attn[33554432];   // [N][512] in point order (already scattered)

// ---------------- packed f32x2 helpers (full-rate fp32 on sm_10x) --------------
__device__ __forceinline__ ull pack2(float x) {
    ull r; asm("mov.b64 %0, {%1, %1};" : "=l"(r) : "f"(x)); return r;
}
__device__ __forceinline__ ull packxy(float x, float y) {
    ull r; asm("mov.b64 %0, {%1, %2};" : "=l"(r) : "f"(x), "f"(y)); return r;
}
__device__ __forceinline__ void ffma2(ull &c, ull a, ull b) {
    asm("fma.rn.f32x2 %0, %1, %2, %0;" : "+l"(c) : "l"(a), "l"(b));
}
__device__ __forceinline__ float2 unpack2(ull v) {
    float2 f; asm("mov.b64 {%0, %1}, %2;" : "=f"(f.x), "=f"(f.y) : "l"(v)); return f;
}

// ---------------------------------------------------------------------------
// GEMM: C[r][c] = sum_k A[row(r)][k] * Bw[c][k] + bias[c]
//   row(r) = gather[r] if GATHER else r.   128x128 tile, BK=16, 256 threads,
//   8x8 per thread (as 8 rows x 4 f32x2 pairs), split 4+4 sub-tiles for
//   conflict-free shared loads.
// ---------------------------------------------------------------------------
template<bool GATHER>
__global__ void __launch_bounds__(256, 2) gemm_tn(
    const float* __restrict__ A, int lda,
    const int*   __restrict__ gather,
    const float* __restrict__ Bw, int K,
    const float* __restrict__ bias,
    float* __restrict__ Cm, int ldc)
{
    __shared__ float As[16][128];
    __shared__ float Bs[16][128];

    const int tid    = threadIdx.x;
    const int rowBlk = blockIdx.y << 7;
    const int colBlk = blockIdx.x << 7;
    const int lm = tid & 127;          // row within tile for loads
    const int lk = (tid >> 7) << 3;    // k sub-offset: 0 or 8

    int arow = rowBlk + lm;
    if (GATHER) arow = gather[arow];
    const float* aptr = A  + (size_t)arow * lda + lk;
    const float* bptr = Bw + (size_t)(colBlk + lm) * K + lk;

    const int ty = tid >> 4, tx = tid & 15;

    ull acc[8][4];
#pragma unroll
    for (int i = 0; i < 8; i++)
#pragma unroll
        for (int j = 0; j < 4; j++) acc[i][j] = 0ull;

    // prefetched global loads
    float4 a0 = *(const float4*)(aptr);
    float4 a1 = *(const float4*)(aptr + 4);
    float4 b0 = *(const float4*)(bptr);
    float4 b1 = *(const float4*)(bptr + 4);

    for (int kb = 0; kb < K; kb += 16) {
        As[lk + 0][lm] = a0.x; As[lk + 1][lm] = a0.y;
        As[lk + 2][lm] = a0.z; As[lk + 3][lm] = a0.w;
        As[lk + 4][lm] = a1.x; As[lk + 5][lm] = a1.y;
        As[lk + 6][lm] = a1.z; As[lk + 7][lm] = a1.w;
        Bs[lk + 0][lm] = b0.x; Bs[lk + 1][lm] = b0.y;
        Bs[lk + 2][lm] = b0.z; Bs[lk + 3][lm] = b0.w;
        Bs[lk + 4][lm] = b1.x; Bs[lk + 5][lm] = b1.y;
        Bs[lk + 6][lm] = b1.z; Bs[lk + 7][lm] = b1.w;
        __syncthreads();

        const bool more = (kb + 16) < K;
        if (more) {
            a0 = *(const float4*)(aptr + kb + 16);
            a1 = *(const float4*)(aptr + kb + 20);
            b0 = *(const float4*)(bptr + kb + 16);
            b1 = *(const float4*)(bptr + kb + 20);
        }

#pragma unroll
        for (int kk = 0; kk < 16; kk++) {
            float4 af0 = *(const float4*)&As[kk][ty << 2];
            float4 af1 = *(const float4*)&As[kk][64 + (ty << 2)];
            const ull* bp0 = (const ull*)&Bs[kk][tx << 2];
            const ull* bp1 = (const ull*)&Bs[kk][64 + (tx << 2)];
            ull bb0 = bp0[0], bb1 = bp0[1], bb2 = bp1[0], bb3 = bp1[1];
            float aa[8] = {af0.x, af0.y, af0.z, af0.w,
                           af1.x, af1.y, af1.z, af1.w};
#pragma unroll
            for (int i = 0; i < 8; i++) {
                ull ai = pack2(aa[i]);
                ffma2(acc[i][0], ai, bb0);
                ffma2(acc[i][1], ai, bb1);
                ffma2(acc[i][2], ai, bb2);
                ffma2(acc[i][3], ai, bb3);
            }
        }
        __syncthreads();
    }

    // epilogue: add bias, store fp32
    const int c0 = tx << 2;
#pragma unroll
    for (int i = 0; i < 8; i++) {
        int r = rowBlk + ((i < 4) ? ((ty << 2) + i) : (64 + (ty << 2) + i - 4));
        float* dst = Cm + (size_t)r * ldc + colBlk;
        const float* bs = bias + colBlk;
        float2 v;
        v = unpack2(acc[i][0]); v.x += bs[c0];          v.y += bs[c0 + 1];      *(float2*)(dst + c0) = v;
        v = unpack2(acc[i][1]); v.x += bs[c0 + 2];      v.y += bs[c0 + 3];      *(float2*)(dst + c0 + 2) = v;
        v = unpack2(acc[i][2]); v.x += bs[64 + c0];     v.y += bs[64 + c0 + 1]; *(float2*)(dst + 64 + c0) = v;
        v = unpack2(acc[i][3]); v.x += bs[64 + c0 + 2]; v.y += bs[64 + c0 + 3]; *(float2*)(dst + 64 + c0 + 2) = v;
    }
}

// ---------------------------------------------------------------------------
// Attention: one block per (window, head). 256 threads.
//   smem float offsets:
//     ksT  [64][132]   @ 0          (k transposed, d-major)
//     S    [128][132]  @ 8448       (scores)
//     qvT              @ 25344      (q transposed [64][132], later v [128][68])
//     rpes [93*8]      @ 34048
//     invs [128]       @ 34792
//     ints: ords[128], gx[128], gy[128], gz[128] @ float-off 34920
// ---------------------------------------------------------------------------
#define SM_KS   0
#define SM_S    8448
#define SM_QV   25344
#define SM_RPE  34048
#define SM_INV  34792
#define SM_INT  34920
#define ATTN_SMEM ((34920 + 512) * 4)

__global__ void __launch_bounds__(256, 1) attn_kernel(
    const float* __restrict__ qkv,
    const float* __restrict__ rpe,
    const int*   __restrict__ gcoord,
    const int*   __restrict__ order,
    float* __restrict__ outg)
{
    extern __shared__ float sm[];
    float* ksT  = sm + SM_KS;
    float* S    = sm + SM_S;
    float* qvT  = sm + SM_QV;
    float* rpes = sm + SM_RPE;
    float* invs = sm + SM_INV;
    int* ords = (int*)(sm + SM_INT);
    int* gx = ords + 128;
    int* gy = gx + 128;
    int* gz = gy + 128;

    const int tid  = threadIdx.x;
    const int w    = blockIdx.x >> 3;
    const int h    = blockIdx.x & 7;
    const float* base = qkv + (size_t)w * 128 * 1536 + h * 64;

    const int lane = tid & 31;
    const int wp   = tid >> 5;

    // ---- load q (pre-scaled) and k, transposed to [d][p] (bank-spread map) ----
#pragma unroll
    for (int r = 0; r < 8; r++) {
        int sub = (r << 5) + lane;             // 0..255 per warp
        int p   = (wp << 4) + (sub & 15);
        int dg  = (sub >> 4) << 2;             // 0,4,...,60
        const float* src = base + (size_t)p * 1536 + dg;
        float4 qv = *(const float4*)src;
        float4 kv = *(const float4*)(src + 512);
        int rb = dg * 132 + p;
        qvT[rb]       = qv.x * SCALEQ;
        qvT[rb + 132] = qv.y * SCALEQ;
        qvT[rb + 264] = qv.z * SCALEQ;
        qvT[rb + 396] = qv.w * SCALEQ;
        ksT[rb]       = kv.x;
        ksT[rb + 132] = kv.y;
        ksT[rb + 264] = kv.z;
        ksT[rb + 396] = kv.w;
    }
    if (tid < 128) ords[tid] = order[(w << 7) + tid];
    for (int i = tid; i < RPE_ROWS * 8; i += 256) rpes[i] = rpe[i];
    __syncthreads();

    if (tid < 128) {
        int o = ords[tid];
        gx[tid] = gcoord[3 * o];
        gy[tid] = gcoord[3 * o + 1];
        gz[tid] = gcoord[3 * o + 2];
    }

    const int ty = tid >> 4, tx = tid & 15;

    // ---- phase 1: S = (q*scale) @ k^T  (128x128, K=64) ----
    {
        ull acc[8][4];
#pragma unroll
        for (int i = 0; i < 8; i++)
#pragma unroll
            for (int j = 0; j < 4; j++) acc[i][j] = 0ull;

#pragma unroll 4
        for (int kk = 0; kk < 64; kk++) {
            const float* qrow = qvT + kk * 132;
            const float* krow = ksT + kk * 132;
            float4 af0 = *(const float4*)(qrow + (ty << 2));
            float4 af1 = *(const float4*)(qrow + 64 + (ty << 2));
            const ull* bp0 = (const ull*)(krow + (tx << 2));
            const ull* bp1 = (const ull*)(krow + 64 + (tx << 2));
            ull bb0 = bp0[0], bb1 = bp0[1], bb2 = bp1[0], bb3 = bp1[1];
            float aa[8] = {af0.x, af0.y, af0.z, af0.w,
                           af1.x, af1.y, af1.z, af1.w};
#pragma unroll
            for (int i = 0; i < 8; i++) {
                ull ai = pack2(aa[i]);
                ffma2(acc[i][0], ai, bb0);
                ffma2(acc[i][1], ai, bb1);
                ffma2(acc[i][2], ai, bb2);
                ffma2(acc[i][3], ai, bb3);
            }
        }
#pragma unroll
        for (int i = 0; i < 8; i++) {
            int rr = (i < 4) ? ((ty << 2) + i) : (64 + (ty << 2) + i - 4);
            float* srow = S + rr * 132;
            float2 v;
            v = unpack2(acc[i][0]); *(float2*)(srow + (tx << 2))          = v;
            v = unpack2(acc[i][1]); *(float2*)(srow + (tx << 2) + 2)      = v;
            v = unpack2(acc[i][2]); *(float2*)(srow + 64 + (tx << 2))     = v;
            v = unpack2(acc[i][3]); *(float2*)(srow + 64 + (tx << 2) + 2) = v;
        }
    }
    __syncthreads();

    // ---- load v into qvT region as vs[128][68] (q no longer needed) ----
#pragma unroll
    for (int r = 0; r < 8; r++) {
        int sub = (r << 5) + lane;
        int p   = (wp << 4) + (sub & 15);
        int dg  = (sub >> 4) << 2;
        float4 vv = *(const float4*)(base + (size_t)p * 1536 + 1024 + dg);
        *(float4*)&qvT[p * 68 + dg] = vv;
    }

    // ---- softmax with RPE bias: 2 threads per row ----
    {
        const int p  = tid >> 1;
        const int hf = tid & 1;
        const int gpx = gx[p], gpy = gy[p], gpz = gz[p];
        float* srow = S + p * 132 + (hf << 6);
        const int cb = hf << 6;
        float mx = -1e30f;
#pragma unroll 8
        for (int c64 = 0; c64 < 64; c64++) {
            int c = cb + c64;
            int i0 = min(max(gpx - gx[c], -POSBND), POSBND) + POSBND;
            int i1 = min(max(gpy - gy[c], -POSBND), POSBND) + POSBND + 31;
            int i2 = min(max(gpz - gz[c], -POSBND), POSBND) + POSBND + 62;
            float b = rpes[i0 * 8 + h] + rpes[i1 * 8 + h] + rpes[i2 * 8 + h];
            float s = srow[c64] + b;
            srow[c64] = s;
            mx = fmaxf(mx, s);
        }
        mx = fmaxf(mx, __shfl_xor_sync(0xffffffffu, mx, 1));
        float sum = 0.f;
#pragma unroll 8
        for (int c64 = 0; c64 < 64; c64++) {
            float e = __expf(srow[c64] - mx);
            srow[c64] = e;
            sum += e;
        }
        sum += __shfl_xor_sync(0xffffffffu, sum, 1);
        if (hf == 0) invs[p] = 1.0f / sum;
    }
    __syncthreads();

    // ---- phase 2: O = S_exp @ V, scale by invs, scatter to point order ----
    // q-loop chunked by 4 so S is read as float4 (12 LDS per 64 FFMA2 -> FMA bound)
    {
        ull acc2[8][2];
        int rof[8];
#pragma unroll
        for (int i = 0; i < 8; i++) {
            acc2[i][0] = 0ull; acc2[i][1] = 0ull;
            rof[i] = ((i < 4) ? ((ty << 2) + i) : (64 + (ty << 2) + i - 4)) * 132;
        }
#pragma unroll 2
        for (int q4 = 0; q4 < 128; q4 += 4) {
            ull bv[4][2];
#pragma unroll
            for (int j = 0; j < 4; j++) {
                float4 b4 = *(const float4*)(qvT + (q4 + j) * 68 + (tx << 2));
                bv[j][0] = packxy(b4.x, b4.y);
                bv[j][1] = packxy(b4.z, b4.w);
            }
#pragma unroll
            for (int i = 0; i < 8; i++) {
                float4 sv = *(const float4*)(S + rof[i] + q4);
                ull a0 = pack2(sv.x), a1 = pack2(sv.y);
                ull a2 = pack2(sv.z), a3 = pack2(sv.w);
                ffma2(acc2[i][0], a0, bv[0][0]); ffma2(acc2[i][1], a0, bv[0][1]);
                ffma2(acc2[i][0], a1, bv[1][0]); ffma2(acc2[i][1], a1, bv[1][1]);
                ffma2(acc2[i][0], a2, bv[2][0]); ffma2(acc2[i][1], a2, bv[2][1]);
                ffma2(acc2[i][0], a3, bv[3][0]); ffma2(acc2[i][1], a3, bv[3][1]);
            }
        }
#pragma unroll
        for (int i = 0; i < 8; i++) {
            int rr = (i < 4) ? ((ty << 2) + i) : (64 + (ty << 2) + i - 4);
            float iv = invs[rr];
            float2 v0 = unpack2(acc2[i][0]);
            float2 v1 = unpack2(acc2[i][1]);
            float4 o = make_float4(v0.x * iv, v0.y * iv, v1.x * iv, v1.y * iv);
            *(float4*)(outg + (size_t)ords[rr] * 512 + (h << 6) + (tx << 2)) = o;
        }
    }
}

// ---------------------------------------------------------------------------
extern "C" void kernel_launch(void* const* d_in, const int* in_sizes, int n_in,
                              void* d_out, int out_size)
{
    const float* feat   = (const float*)d_in[0];
    const float* w_qkv  = (const float*)d_in[1];
    const float* b_qkv  = (const float*)d_in[2];
    const float* w_proj = (const float*)d_in[3];
    const float* b_proj = (const float*)d_in[4];
    const float* rpe    = (const float*)d_in[5];
    const int*   gcoord = (const int*)d_in[6];
    const int*   order  = (const int*)d_in[7];
    // d_in[8] = inverse, unused (order fully determines the scatter)
    float* out = (float*)d_out;

    void* p0; cudaGetSymbolAddress(&p0, g_qkv);
    void* p1; cudaGetSymbolAddress(&p1, g_attn);
    float* qkv  = (float*)p0;
    float* attn = (float*)p1;

    cudaFuncSetAttribute(attn_kernel,
                         cudaFuncAttributeMaxDynamicSharedMemorySize, ATTN_SMEM);

    // 1) gathered QKV projection -> g_qkv [N][1536] in serialized order
    gemm_tn<true><<<dim3(12, 512), 256>>>(feat, 512, order, w_qkv, 512,
                                          b_qkv, qkv, 1536);
    // 2) windowed attention -> g_attn [N][512] in point order
    attn_kernel<<<NWIN * NH, 256, ATTN_SMEM>>>(qkv, rpe, gcoord, order, attn);
    // 3) output projection -> d_out
    gemm_tn<false><<<dim3(4, 512), 256>>>(attn, 512, nullptr, w_proj, 512,
                                          b_proj, out, 512);
}

// round 5
// speedup vs baseline: 1.4550x; 1.4550x over previous
#include <cuda_runtime.h>
#include <cuda_bf16.h>
#include <cstdint>

typedef unsigned long long ull;
typedef unsigned int u32;

#define NPTS    65536
#define NWIN    512
#define NH      8
#define POSBND  15
#define RPE_ROWS 93
#define SCALEQ  0.125f

// ---------------- device scratch (no allocation APIs allowed) ----------------
__device__ float          g_qkv[100663296];   // [N][1536] fp32, point order
__device__ unsigned short g_fh[33554432];     // feat hi/lo bf16 planes [N][512]
__device__ unsigned short g_fl[33554432];
__device__ unsigned short g_ah[33554432];     // attn out hi/lo planes [N][512]
__device__ unsigned short g_al[33554432];
__device__ unsigned short g_wqh[786432];      // w_qkv planes [1536][512]
__device__ unsigned short g_wql[786432];
__device__ unsigned short g_wph[262144];      // w_proj planes [512][512]
__device__ unsigned short g_wpl[262144];

// ---------------- PTX helpers (all sm_80-era, compute_100-safe) ----------------
__device__ __forceinline__ u32 s2u(const void* p) {
    u32 a; asm("{ .reg .u64 t; cvta.to.shared.u64 t, %1; cvt.u32.u64 %0, t; }"
               : "=r"(a) : "l"(p)); return a;
}
__device__ __forceinline__ void cp16(u32 dst, const void* src) {
    asm volatile("cp.async.cg.shared.global [%0], [%1], 16;" :: "r"(dst), "l"(src) : "memory");
}
__device__ __forceinline__ void cp_commit() {
    asm volatile("cp.async.commit_group;" ::: "memory");
}
__device__ __forceinline__ void ldsm4(u32* r, u32 addr) {
    asm volatile("ldmatrix.sync.aligned.m8n8.x4.shared.b16 {%0,%1,%2,%3}, [%4];"
        : "=r"(r[0]), "=r"(r[1]), "=r"(r[2]), "=r"(r[3]) : "r"(addr));
}
__device__ __forceinline__ void ldsm2(u32* r, u32 addr) {
    asm volatile("ldmatrix.sync.aligned.m8n8.x2.shared.b16 {%0,%1}, [%2];"
        : "=r"(r[0]), "=r"(r[1]) : "r"(addr));
}
__device__ __forceinline__ void mma16816(float* c, const u32* a, const u32* b) {
    asm volatile("mma.sync.aligned.m16n8k16.row.col.f32.bf16.bf16.f32 "
        "{%0,%1,%2,%3}, {%4,%5,%6,%7}, {%8,%9}, {%0,%1,%2,%3};"
        : "+f"(c[0]), "+f"(c[1]), "+f"(c[2]), "+f"(c[3])
        : "r"(a[0]), "r"(a[1]), "r"(a[2]), "r"(a[3]), "r"(b[0]), "r"(b[1]));
}

// ---------------- fp32 -> bf16 hi/lo split (elementwise) ----------------
__global__ void __launch_bounds__(256) split_kernel(
    const float* __restrict__ x,
    unsigned short* __restrict__ hi, unsigned short* __restrict__ lo)
{
    int i = (blockIdx.x * 256 + threadIdx.x) * 4;
    float4 v = *(const float4*)(x + i);
    __nv_bfloat16 h0 = __float2bfloat16_rn(v.x), h1 = __float2bfloat16_rn(v.y),
                  h2 = __float2bfloat16_rn(v.z), h3 = __float2bfloat16_rn(v.w);
    *(ushort4*)(hi + i) = make_ushort4(
        __bfloat16_as_ushort(h0), __bfloat16_as_ushort(h1),
        __bfloat16_as_ushort(h2), __bfloat16_as_ushort(h3));
    __nv_bfloat16 l0 = __float2bfloat16_rn(v.x - __bfloat162float(h0));
    __nv_bfloat16 l1 = __float2bfloat16_rn(v.y - __bfloat162float(h1));
    __nv_bfloat16 l2 = __float2bfloat16_rn(v.z - __bfloat162float(h2));
    __nv_bfloat16 l3 = __float2bfloat16_rn(v.w - __bfloat162float(h3));
    *(ushort4*)(lo + i) = make_ushort4(
        __bfloat16_as_ushort(l0), __bfloat16_as_ushort(l1),
        __bfloat16_as_ushort(l2), __bfloat16_as_ushort(l3));
}

// ---------------------------------------------------------------------------
// mma.sync bf16x3 GEMM:  C[m][n] = sum_k (Ah+Al)[m][k]*(Bh+Bl)[n][k] + bias[n]
//   128x128 tile, BK=32, K=512, 256 threads (8 warps as 2m x 4n, 64x32/warp),
//   3 products per acc (AhBh + AhBl + AlBh), cp.async double buffer.
//   smem per stage: 4 planes (Ah,Al,Bh,Bl), each [128][40] bf16 (pitch 80B:
//   rows r -> start bank 20r mod 32, all 8 distinct -> ldmatrix conflict-free)
// ---------------------------------------------------------------------------
#define PLANE_B  10240            // 128 * 80
#define STAGE_B  40960            // 4 planes
#define GSM_TOTAL (2 * STAGE_B)   // 81920

__global__ void __launch_bounds__(256, 1) gemm_bf16x3(
    const __nv_bfloat16* __restrict__ Ah, const __nv_bfloat16* __restrict__ Al,
    const __nv_bfloat16* __restrict__ Bh, const __nv_bfloat16* __restrict__ Bl,
    const float* __restrict__ bias, float* __restrict__ C, int ldc)
{
    extern __shared__ char smem[];
    const u32 sb = s2u(smem);

    const int tid  = threadIdx.x;
    const int lane = tid & 31;
    const int wid  = tid >> 5;
    const int wm   = wid >> 2;        // 0..1 -> m offset 64*wm
    const int wn   = wid & 3;         // 0..3 -> n offset 32*wn
    const int rowBlk = blockIdx.y << 7, colBlk = blockIdx.x << 7;

    // ---- cp.async fill mapping: thread t -> row t>>1, 2x16B units ----
    const int crow = tid >> 1;
    const int u0   = (tid & 1) * 2;   // 16B-unit index: u0, u0+1
    const u32 dst_row = (u32)(crow * 80);
    const __nv_bfloat16* pa_h = Ah + (size_t)(rowBlk + crow) * 512 + u0 * 8;
    const __nv_bfloat16* pa_l = Al + (size_t)(rowBlk + crow) * 512 + u0 * 8;
    const __nv_bfloat16* pb_h = Bh + (size_t)(colBlk + crow) * 512 + u0 * 8;
    const __nv_bfloat16* pb_l = Bl + (size_t)(colBlk + crow) * 512 + u0 * 8;

    auto fill = [&](int st, int c) {
        u32 base = sb + st * STAGE_B + dst_row + u0 * 16;
        const __nv_bfloat16* s0 = pa_h + c * 32;
        const __nv_bfloat16* s1 = pa_l + c * 32;
        const __nv_bfloat16* s2 = pb_h + c * 32;
        const __nv_bfloat16* s3 = pb_l + c * 32;
        cp16(base,                  s0); cp16(base + 16,                  s0 + 8);
        cp16(base + PLANE_B,        s1); cp16(base + PLANE_B + 16,        s1 + 8);
        cp16(base + 2 * PLANE_B,    s2); cp16(base + 2 * PLANE_B + 16,    s2 + 8);
        cp16(base + 3 * PLANE_B,    s3); cp16(base + 3 * PLANE_B + 16,    s3 + 8);
        cp_commit();
    };

    float acc[4][4][4];
#pragma unroll
    for (int mi = 0; mi < 4; mi++)
#pragma unroll
        for (int ni = 0; ni < 4; ni++)
#pragma unroll
            for (int j = 0; j < 4; j++) acc[mi][ni][j] = 0.f;

    // ldmatrix address components
    const int a_row = (wm << 6) + ((lane >> 3) & 1) * 8 + (lane & 7); // + mi*16
    const int a_k8  = (lane >> 4) * 8;                                // halves
    const int b_row = (wn << 5) + (lane & 7);                         // + ni*8
    const int b_k8  = ((lane >> 3) & 1) * 8;

    fill(0, 0);
    fill(1, 1);

    const int KI = 16;   // 512 / 32
#pragma unroll 1
    for (int c = 0; c < KI; c++) {
        const int buf = c & 1;
        if (c + 1 < KI) asm volatile("cp.async.wait_group 1;" ::: "memory");
        else            asm volatile("cp.async.wait_group 0;" ::: "memory");
        __syncthreads();

        const u32 As_h = sb + buf * STAGE_B;
        const u32 As_l = As_h + PLANE_B;
        const u32 Bs_h = As_h + 2 * PLANE_B;
        const u32 Bs_l = As_h + 3 * PLANE_B;

#pragma unroll
        for (int ks = 0; ks < 2; ks++) {
            const u32 a_off = (u32)(a_row * 80 + (ks * 16 + a_k8) * 2);
            const u32 b_off = (u32)(b_row * 80 + (ks * 16 + b_k8) * 2);
            u32 ah[4][4], al[4][4], bh[4][2], bl[4][2];
#pragma unroll
            for (int mi = 0; mi < 4; mi++) {
                ldsm4(ah[mi], As_h + a_off + mi * 16 * 80);
                ldsm4(al[mi], As_l + a_off + mi * 16 * 80);
            }
#pragma unroll
            for (int ni = 0; ni < 4; ni++) {
                ldsm2(bh[ni], Bs_h + b_off + ni * 8 * 80);
                ldsm2(bl[ni], Bs_l + b_off + ni * 8 * 80);
            }
#pragma unroll
            for (int mi = 0; mi < 4; mi++)
#pragma unroll
                for (int ni = 0; ni < 4; ni++) {
                    mma16816(acc[mi][ni], ah[mi], bh[ni]);
                    mma16816(acc[mi][ni], ah[mi], bl[ni]);
                    mma16816(acc[mi][ni], al[mi], bh[ni]);
                }
        }
        __syncthreads();
        if (c + 2 < KI) fill(buf, c + 2);
    }

    // ---- epilogue: add bias, store fp32 ----
    const int mrow = rowBlk + (wm << 6) + (lane >> 2);
    const int ncol = colBlk + (wn << 5) + (lane & 3) * 2;
#pragma unroll
    for (int ni = 0; ni < 4; ni++) {
        const int n0 = ncol + ni * 8;
        const float b0 = bias[n0], b1 = bias[n0 + 1];
#pragma unroll
        for (int mi = 0; mi < 4; mi++) {
            float* d0 = C + (size_t)(mrow + mi * 16) * ldc + n0;
            float* d1 = d0 + 8 * ldc;
            float2 v0 = make_float2(acc[mi][ni][0] + b0, acc[mi][ni][1] + b1);
            float2 v1 = make_float2(acc[mi][ni][2] + b0, acc[mi][ni][3] + b1);
            *(float2*)d0 = v0;
            *(float2*)d1 = v1;
        }
    }
}

// ---------------- packed f32x2 helpers (attention math) ----------------
__device__ __forceinline__ ull pack2(float x) {
    ull r; asm("mov.b64 %0, {%1, %1};" : "=l"(r) : "f"(x)); return r;
}
__device__ __forceinline__ ull packxy(float x, float y) {
    ull r; asm("mov.b64 %0, {%1, %2};" : "=l"(r) : "f"(x), "f"(y)); return r;
}
__device__ __forceinline__ void ffma2(ull &c, ull a, ull b) {
    asm("fma.rn.f32x2 %0, %1, %2, %0;" : "+l"(c) : "l"(a), "l"(b));
}
__device__ __forceinline__ float2 unpack2(ull v) {
    float2 f; asm("mov.b64 {%0, %1}, %2;" : "=f"(f.x), "=f"(f.y) : "l"(v)); return f;
}

// ---------------------------------------------------------------------------
// Attention: one block per (window, head). Gathers qkv rows via order[];
// writes output as bf16 hi/lo planes in point order (proj GEMM A operand).
// ---------------------------------------------------------------------------
#define SM_KS   0
#define SM_S    8448
#define SM_QV   25344
#define SM_RPE  34048
#define SM_INV  34792
#define SM_INT  34920
#define ATTN_SMEM ((34920 + 512) * 4)

__global__ void __launch_bounds__(256, 1) attn_kernel(
    const float* __restrict__ qkv,
    const float* __restrict__ rpe,
    const int*   __restrict__ gcoord,
    const int*   __restrict__ order,
    unsigned short* __restrict__ oh,
    unsigned short* __restrict__ ol)
{
    extern __shared__ float sm[];
    float* ksT  = sm + SM_KS;
    float* S    = sm + SM_S;
    float* qvT  = sm + SM_QV;
    float* rpes = sm + SM_RPE;
    float* invs = sm + SM_INV;
    int* ords = (int*)(sm + SM_INT);
    int* gx = ords + 128;
    int* gy = gx + 128;
    int* gz = gy + 128;

    const int tid  = threadIdx.x;
    const int w    = blockIdx.x >> 3;
    const int h    = blockIdx.x & 7;
    const int lane = tid & 31;
    const int wp   = tid >> 5;

    if (tid < 128) ords[tid] = order[(w << 7) + tid];
    for (int i = tid; i < RPE_ROWS * 8; i += 256) rpes[i] = rpe[i];
    __syncthreads();

    if (tid < 128) {
        int o = ords[tid];
        gx[tid] = gcoord[3 * o];
        gy[tid] = gcoord[3 * o + 1];
        gz[tid] = gcoord[3 * o + 2];
    }

    // ---- gather q (pre-scaled) and k, transposed to [d][p] ----
#pragma unroll
    for (int r = 0; r < 8; r++) {
        int sub = (r << 5) + lane;
        int p   = (wp << 4) + (sub & 15);
        int dg  = (sub >> 4) << 2;
        const float* src = qkv + (size_t)ords[p] * 1536 + h * 64 + dg;
        float4 qv = *(const float4*)src;
        float4 kv = *(const float4*)(src + 512);
        int rb = dg * 132 + p;
        qvT[rb]       = qv.x * SCALEQ;
        qvT[rb + 132] = qv.y * SCALEQ;
        qvT[rb + 264] = qv.z * SCALEQ;
        qvT[rb + 396] = qv.w * SCALEQ;
        ksT[rb]       = kv.x;
        ksT[rb + 132] = kv.y;
        ksT[rb + 264] = kv.z;
        ksT[rb + 396] = kv.w;
    }
    __syncthreads();

    const int ty = tid >> 4, tx = tid & 15;

    // ---- phase 1: S = (q*scale) @ k^T ----
    {
        ull acc[8][4];
#pragma unroll
        for (int i = 0; i < 8; i++)
#pragma unroll
            for (int j = 0; j < 4; j++) acc[i][j] = 0ull;

#pragma unroll 4
        for (int kk = 0; kk < 64; kk++) {
            const float* qrow = qvT + kk * 132;
            const float* krow = ksT + kk * 132;
            float4 af0 = *(const float4*)(qrow + (ty << 2));
            float4 af1 = *(const float4*)(qrow + 64 + (ty << 2));
            const ull* bp0 = (const ull*)(krow + (tx << 2));
            const ull* bp1 = (const ull*)(krow + 64 + (tx << 2));
            ull bb0 = bp0[0], bb1 = bp0[1], bb2 = bp1[0], bb3 = bp1[1];
            float aa[8] = {af0.x, af0.y, af0.z, af0.w,
                           af1.x, af1.y, af1.z, af1.w};
#pragma unroll
            for (int i = 0; i < 8; i++) {
                ull ai = pack2(aa[i]);
                ffma2(acc[i][0], ai, bb0);
                ffma2(acc[i][1], ai, bb1);
                ffma2(acc[i][2], ai, bb2);
                ffma2(acc[i][3], ai, bb3);
            }
        }
#pragma unroll
        for (int i = 0; i < 8; i++) {
            int rr = (i < 4) ? ((ty << 2) + i) : (64 + (ty << 2) + i - 4);
            float* srow = S + rr * 132;
            float2 v;
            v = unpack2(acc[i][0]); *(float2*)(srow + (tx << 2))          = v;
            v = unpack2(acc[i][1]); *(float2*)(srow + (tx << 2) + 2)      = v;
            v = unpack2(acc[i][2]); *(float2*)(srow + 64 + (tx << 2))     = v;
            v = unpack2(acc[i][3]); *(float2*)(srow + 64 + (tx << 2) + 2) = v;
        }
    }
    __syncthreads();

    // ---- gather v into qvT region as vs[128][68] ----
#pragma unroll
    for (int r = 0; r < 8; r++) {
        int sub = (r << 5) + lane;
        int p   = (wp << 4) + (sub & 15);
        int dg  = (sub >> 4) << 2;
        float4 vv = *(const float4*)(qkv + (size_t)ords[p] * 1536 + h * 64 + 1024 + dg);
        *(float4*)&qvT[p * 68 + dg] = vv;
    }

    // ---- softmax with RPE bias: 2 threads per row ----
    {
        const int p  = tid >> 1;
        const int hf = tid & 1;
        const int gpx = gx[p], gpy = gy[p], gpz = gz[p];
        float* srow = S + p * 132 + (hf << 6);
        const int cb = hf << 6;
        float mx = -1e30f;
#pragma unroll 8
        for (int c64 = 0; c64 < 64; c64++) {
            int c = cb + c64;
            int i0 = min(max(gpx - gx[c], -POSBND), POSBND) + POSBND;
            int i1 = min(max(gpy - gy[c], -POSBND), POSBND) + POSBND + 31;
            int i2 = min(max(gpz - gz[c], -POSBND), POSBND) + POSBND + 62;
            float b = rpes[i0 * 8 + h] + rpes[i1 * 8 + h] + rpes[i2 * 8 + h];
            float s = srow[c64] + b;
            srow[c64] = s;
            mx = fmaxf(mx, s);
        }
        mx = fmaxf(mx, __shfl_xor_sync(0xffffffffu, mx, 1));
        float sum = 0.f;
#pragma unroll 8
        for (int c64 = 0; c64 < 64; c64++) {
            float e = __expf(srow[c64] - mx);
            srow[c64] = e;
            sum += e;
        }
        sum += __shfl_xor_sync(0xffffffffu, sum, 1);
        if (hf == 0) invs[p] = 1.0f / sum;
    }
    __syncthreads();

    // ---- phase 2: O = S_exp @ V, scale, split to bf16 hi/lo planes ----
    {
        ull acc2[8][2];
        int rof[8];
#pragma unroll
        for (int i = 0; i < 8; i++) {
            acc2[i][0] = 0ull; acc2[i][1] = 0ull;
            rof[i] = ((i < 4) ? ((ty << 2) + i) : (64 + (ty << 2) + i - 4)) * 132;
        }
#pragma unroll 2
        for (int q4 = 0; q4 < 128; q4 += 4) {
            ull bv[4][2];
#pragma unroll
            for (int j = 0; j < 4; j++) {
                float4 b4 = *(const float4*)(qvT + (q4 + j) * 68 + (tx << 2));
                bv[j][0] = packxy(b4.x, b4.y);
                bv[j][1] = packxy(b4.z, b4.w);
            }
#pragma unroll
            for (int i = 0; i < 8; i++) {
                float4 sv = *(const float4*)(S + rof[i] + q4);
                ull a0 = pack2(sv.x), a1 = pack2(sv.y);
                ull a2 = pack2(sv.z), a3 = pack2(sv.w);
                ffma2(acc2[i][0], a0, bv[0][0]); ffma2(acc2[i][1], a0, bv[0][1]);
                ffma2(acc2[i][0], a1, bv[1][0]); ffma2(acc2[i][1], a1, bv[1][1]);
                ffma2(acc2[i][0], a2, bv[2][0]); ffma2(acc2[i][1], a2, bv[2][1]);
                ffma2(acc2[i][0], a3, bv[3][0]); ffma2(acc2[i][1], a3, bv[3][1]);
            }
        }
#pragma unroll
        for (int i = 0; i < 8; i++) {
            int rr = (i < 4) ? ((ty << 2) + i) : (64 + (ty << 2) + i - 4);
            float iv = invs[rr];
            float2 v0 = unpack2(acc2[i][0]);
            float2 v1 = unpack2(acc2[i][1]);
            float o0 = v0.x * iv, o1 = v0.y * iv, o2 = v1.x * iv, o3 = v1.y * iv;
            size_t off = (size_t)ords[rr] * 512 + (h << 6) + (tx << 2);
            __nv_bfloat16 h0 = __float2bfloat16_rn(o0), h1 = __float2bfloat16_rn(o1),
                          h2 = __float2bfloat16_rn(o2), h3 = __float2bfloat16_rn(o3);
            *(ushort4*)(oh + off) = make_ushort4(
                __bfloat16_as_ushort(h0), __bfloat16_as_ushort(h1),
                __bfloat16_as_ushort(h2), __bfloat16_as_ushort(h3));
            __nv_bfloat16 l0 = __float2bfloat16_rn(o0 - __bfloat162float(h0));
            __nv_bfloat16 l1 = __float2bfloat16_rn(o1 - __bfloat162float(h1));
            __nv_bfloat16 l2 = __float2bfloat16_rn(o2 - __bfloat162float(h2));
            __nv_bfloat16 l3 = __float2bfloat16_rn(o3 - __bfloat162float(h3));
            *(ushort4*)(ol + off) = make_ushort4(
                __bfloat16_as_ushort(l0), __bfloat16_as_ushort(l1),
                __bfloat16_as_ushort(l2), __bfloat16_as_ushort(l3));
        }
    }
}

// ---------------------------------------------------------------------------
extern "C" void kernel_launch(void* const* d_in, const int* in_sizes, int n_in,
                              void* d_out, int out_size)
{
    const float* feat   = (const float*)d_in[0];
    const float* w_qkv  = (const float*)d_in[1];
    const float* b_qkv  = (const float*)d_in[2];
    const float* w_proj = (const float*)d_in[3];
    const float* b_proj = (const float*)d_in[4];
    const float* rpe    = (const float*)d_in[5];
    const int*   gcoord = (const int*)d_in[6];
    const int*   order  = (const int*)d_in[7];
    float* out = (float*)d_out;

    void *pqkv, *pfh, *pfl, *pah, *pal, *pwqh, *pwql, *pwph, *pwpl;
    cudaGetSymbolAddress(&pqkv, g_qkv);
    cudaGetSymbolAddress(&pfh, g_fh);   cudaGetSymbolAddress(&pfl, g_fl);
    cudaGetSymbolAddress(&pah, g_ah);   cudaGetSymbolAddress(&pal, g_al);
    cudaGetSymbolAddress(&pwqh, g_wqh); cudaGetSymbolAddress(&pwql, g_wql);
    cudaGetSymbolAddress(&pwph, g_wph); cudaGetSymbolAddress(&pwpl, g_wpl);

    cudaFuncSetAttribute(attn_kernel,
                         cudaFuncAttributeMaxDynamicSharedMemorySize, ATTN_SMEM);
    cudaFuncSetAttribute(gemm_bf16x3,
                         cudaFuncAttributeMaxDynamicSharedMemorySize, GSM_TOTAL);

    // 1) split fp32 operands into bf16 hi/lo planes
    split_kernel<<<32768, 256>>>(feat,   (unsigned short*)pfh,  (unsigned short*)pfl);
    split_kernel<<<768,   256>>>(w_qkv,  (unsigned short*)pwqh, (unsigned short*)pwql);
    split_kernel<<<256,   256>>>(w_proj, (unsigned short*)pwph, (unsigned short*)pwpl);

    // 2) dense QKV projection (mma.sync bf16x3) -> g_qkv [N][1536] (point order)
    gemm_bf16x3<<<dim3(12, 512), 256, GSM_TOTAL>>>(
        (const __nv_bfloat16*)pfh,  (const __nv_bfloat16*)pfl,
        (const __nv_bfloat16*)pwqh, (const __nv_bfloat16*)pwql,
        b_qkv, (float*)pqkv, 1536);

    // 3) windowed attention (gathers via order) -> bf16 hi/lo planes (point order)
    attn_kernel<<<NWIN * NH, 256, ATTN_SMEM>>>(
        (const float*)pqkv, rpe, gcoord, order,
        (unsigned short*)pah, (unsigned short*)pal);

    // 4) output projection (mma.sync bf16x3) -> d_out
    gemm_bf16x3<<<dim3(4, 512), 256, GSM_TOTAL>>>(
        (const __nv_bfloat16*)pah,  (const __nv_bfloat16*)pal,
        (const __nv_bfloat16*)pwph, (const __nv_bfloat16*)pwpl,
        b_proj, out, 512);
}

// round 6
// speedup vs baseline: 1.5866x; 1.0904x over previous
#include <cuda_runtime.h>
#include <cuda_bf16.h>
#include <cstdint>

typedef unsigned long long ull;
typedef unsigned int u32;

#define NPTS    65536
#define NWIN    512
#define NH      8
#define POSBND  15
#define RPE_ROWS 93
#define SCALEQ  0.125f

// ---------------- device scratch (no allocation APIs allowed) ----------------
__device__ float          g_qkv[100663296];   // [N][1536] fp32, point order
__device__ unsigned short g_fh[33554432];     // feat hi/lo bf16 planes [N][512]
__device__ unsigned short g_fl[33554432];
__device__ unsigned short g_ah[33554432];     // attn out hi/lo planes [N][512]
__device__ unsigned short g_al[33554432];
__device__ unsigned short g_wqh[786432];      // w_qkv planes [1536][512]
__device__ unsigned short g_wql[786432];
__device__ unsigned short g_wph[262144];      // w_proj planes [512][512]
__device__ unsigned short g_wpl[262144];

// ---------------- PTX helpers (all sm_80-era, compute_100-safe) ----------------
__device__ __forceinline__ u32 s2u(const void* p) {
    u32 a; asm("{ .reg .u64 t; cvta.to.shared.u64 t, %1; cvt.u32.u64 %0, t; }"
               : "=r"(a) : "l"(p)); return a;
}
__device__ __forceinline__ void cp16(u32 dst, const void* src) {
    asm volatile("cp.async.cg.shared.global [%0], [%1], 16;" :: "r"(dst), "l"(src) : "memory");
}
__device__ __forceinline__ void cp_commit() {
    asm volatile("cp.async.commit_group;" ::: "memory");
}
__device__ __forceinline__ void ldsm4(u32* r, u32 addr) {
    asm volatile("ldmatrix.sync.aligned.m8n8.x4.shared.b16 {%0,%1,%2,%3}, [%4];"
        : "=r"(r[0]), "=r"(r[1]), "=r"(r[2]), "=r"(r[3]) : "r"(addr));
}
__device__ __forceinline__ void ldsm2(u32* r, u32 addr) {
    asm volatile("ldmatrix.sync.aligned.m8n8.x2.shared.b16 {%0,%1}, [%2];"
        : "=r"(r[0]), "=r"(r[1]) : "r"(addr));
}
__device__ __forceinline__ void mma16816(float* c, const u32* a, const u32* b) {
    asm volatile("mma.sync.aligned.m16n8k16.row.col.f32.bf16.bf16.f32 "
        "{%0,%1,%2,%3}, {%4,%5,%6,%7}, {%8,%9}, {%0,%1,%2,%3};"
        : "+f"(c[0]), "+f"(c[1]), "+f"(c[2]), "+f"(c[3])
        : "r"(a[0]), "r"(a[1]), "r"(a[2]), "r"(a[3]), "r"(b[0]), "r"(b[1]));
}

// ---------------- fp32 -> bf16 hi/lo split (elementwise) ----------------
__global__ void __launch_bounds__(256) split_kernel(
    const float* __restrict__ x,
    unsigned short* __restrict__ hi, unsigned short* __restrict__ lo)
{
    int i = (blockIdx.x * 256 + threadIdx.x) * 4;
    float4 v = *(const float4*)(x + i);
    __nv_bfloat16 h0 = __float2bfloat16_rn(v.x), h1 = __float2bfloat16_rn(v.y),
                  h2 = __float2bfloat16_rn(v.z), h3 = __float2bfloat16_rn(v.w);
    *(ushort4*)(hi + i) = make_ushort4(
        __bfloat16_as_ushort(h0), __bfloat16_as_ushort(h1),
        __bfloat16_as_ushort(h2), __bfloat16_as_ushort(h3));
    __nv_bfloat16 l0 = __float2bfloat16_rn(v.x - __bfloat162float(h0));
    __nv_bfloat16 l1 = __float2bfloat16_rn(v.y - __bfloat162float(h1));
    __nv_bfloat16 l2 = __float2bfloat16_rn(v.z - __bfloat162float(h2));
    __nv_bfloat16 l3 = __float2bfloat16_rn(v.w - __bfloat162float(h3));
    *(ushort4*)(lo + i) = make_ushort4(
        __bfloat16_as_ushort(l0), __bfloat16_as_ushort(l1),
        __bfloat16_as_ushort(l2), __bfloat16_as_ushort(l3));
}

// ---------------------------------------------------------------------------
// mma.sync bf16x3 GEMM:  C[m][n] = sum_k (Ah+Al)[m][k]*(Bh+Bl)[n][k] + bias[n]
//   128x128 tile, BK=32, K=512, 256 threads (8 warps as 2m x 4n, 64x32/warp),
//   3 products per acc (AhBh + AhBl + AlBh), cp.async double buffer.
//   A-fragments loaded per-mi to cap live registers -> 2 CTAs/SM.
// ---------------------------------------------------------------------------
#define PLANE_B  10240            // 128 * 80
#define STAGE_B  40960            // 4 planes
#define GSM_TOTAL (2 * STAGE_B)   // 81920

__global__ void __launch_bounds__(256, 2) gemm_bf16x3(
    const __nv_bfloat16* __restrict__ Ah, const __nv_bfloat16* __restrict__ Al,
    const __nv_bfloat16* __restrict__ Bh, const __nv_bfloat16* __restrict__ Bl,
    const float* __restrict__ bias, float* __restrict__ C, int ldc)
{
    extern __shared__ char smem[];
    const u32 sb = s2u(smem);

    const int tid  = threadIdx.x;
    const int lane = tid & 31;
    const int wid  = tid >> 5;
    const int wm   = wid >> 2;        // 0..1 -> m offset 64*wm
    const int wn   = wid & 3;         // 0..3 -> n offset 32*wn
    const int rowBlk = blockIdx.y << 7, colBlk = blockIdx.x << 7;

    // ---- cp.async fill mapping: thread t -> row t>>1, 2x16B units ----
    const int crow = tid >> 1;
    const int u0   = (tid & 1) * 2;   // 16B-unit index: u0, u0+1
    const u32 dst_row = (u32)(crow * 80);
    const __nv_bfloat16* pa_h = Ah + (size_t)(rowBlk + crow) * 512 + u0 * 8;
    const __nv_bfloat16* pa_l = Al + (size_t)(rowBlk + crow) * 512 + u0 * 8;
    const __nv_bfloat16* pb_h = Bh + (size_t)(colBlk + crow) * 512 + u0 * 8;
    const __nv_bfloat16* pb_l = Bl + (size_t)(colBlk + crow) * 512 + u0 * 8;

    auto fill = [&](int st, int c) {
        u32 base = sb + st * STAGE_B + dst_row + u0 * 16;
        const __nv_bfloat16* s0 = pa_h + c * 32;
        const __nv_bfloat16* s1 = pa_l + c * 32;
        const __nv_bfloat16* s2 = pb_h + c * 32;
        const __nv_bfloat16* s3 = pb_l + c * 32;
        cp16(base,                  s0); cp16(base + 16,                  s0 + 8);
        cp16(base + PLANE_B,        s1); cp16(base + PLANE_B + 16,        s1 + 8);
        cp16(base + 2 * PLANE_B,    s2); cp16(base + 2 * PLANE_B + 16,    s2 + 8);
        cp16(base + 3 * PLANE_B,    s3); cp16(base + 3 * PLANE_B + 16,    s3 + 8);
        cp_commit();
    };

    float acc[4][4][4];
#pragma unroll
    for (int mi = 0; mi < 4; mi++)
#pragma unroll
        for (int ni = 0; ni < 4; ni++)
#pragma unroll
            for (int j = 0; j < 4; j++) acc[mi][ni][j] = 0.f;

    // ldmatrix address components
    const int a_row = (wm << 6) + ((lane >> 3) & 1) * 8 + (lane & 7); // + mi*16
    const int a_k8  = (lane >> 4) * 8;                                // halves
    const int b_row = (wn << 5) + (lane & 7);                         // + ni*8
    const int b_k8  = ((lane >> 3) & 1) * 8;

    fill(0, 0);
    fill(1, 1);

    const int KI = 16;   // 512 / 32
#pragma unroll 1
    for (int c = 0; c < KI; c++) {
        const int buf = c & 1;
        if (c + 1 < KI) asm volatile("cp.async.wait_group 1;" ::: "memory");
        else            asm volatile("cp.async.wait_group 0;" ::: "memory");
        __syncthreads();

        const u32 As_h = sb + buf * STAGE_B;
        const u32 As_l = As_h + PLANE_B;
        const u32 Bs_h = As_h + 2 * PLANE_B;
        const u32 Bs_l = As_h + 3 * PLANE_B;

#pragma unroll
        for (int ks = 0; ks < 2; ks++) {
            const u32 a_off = (u32)(a_row * 80 + (ks * 16 + a_k8) * 2);
            const u32 b_off = (u32)(b_row * 80 + (ks * 16 + b_k8) * 2);
            u32 bh[4][2], bl[4][2];
#pragma unroll
            for (int ni = 0; ni < 4; ni++) {
                ldsm2(bh[ni], Bs_h + b_off + ni * 8 * 80);
                ldsm2(bl[ni], Bs_l + b_off + ni * 8 * 80);
            }
#pragma unroll
            for (int mi = 0; mi < 4; mi++) {
                u32 ah[4], al[4];
                ldsm4(ah, As_h + a_off + mi * 16 * 80);
                ldsm4(al, As_l + a_off + mi * 16 * 80);
#pragma unroll
                for (int ni = 0; ni < 4; ni++) {
                    mma16816(acc[mi][ni], ah, bh[ni]);
                    mma16816(acc[mi][ni], ah, bl[ni]);
                    mma16816(acc[mi][ni], al, bh[ni]);
                }
            }
        }
        __syncthreads();
        if (c + 2 < KI) fill(buf, c + 2);
    }

    // ---- epilogue: add bias, store fp32 ----
    const int mrow = rowBlk + (wm << 6) + (lane >> 2);
    const int ncol = colBlk + (wn << 5) + (lane & 3) * 2;
#pragma unroll
    for (int ni = 0; ni < 4; ni++) {
        const int n0 = ncol + ni * 8;
        const float b0 = bias[n0], b1 = bias[n0 + 1];
#pragma unroll
        for (int mi = 0; mi < 4; mi++) {
            float* d0 = C + (size_t)(mrow + mi * 16) * ldc + n0;
            float* d1 = d0 + 8 * ldc;
            float2 v0 = make_float2(acc[mi][ni][0] + b0, acc[mi][ni][1] + b1);
            float2 v1 = make_float2(acc[mi][ni][2] + b0, acc[mi][ni][3] + b1);
            *(float2*)d0 = v0;
            *(float2*)d1 = v1;
        }
    }
}

// ---------------- packed f32x2 helpers (attention math) ----------------
__device__ __forceinline__ ull pack2(float x) {
    ull r; asm("mov.b64 %0, {%1, %1};" : "=l"(r) : "f"(x)); return r;
}
__device__ __forceinline__ ull packxy(float x, float y) {
    ull r; asm("mov.b64 %0, {%1, %2};" : "=l"(r) : "f"(x), "f"(y)); return r;
}
__device__ __forceinline__ void ffma2(ull &c, ull a, ull b) {
    asm("fma.rn.f32x2 %0, %1, %2, %0;" : "+l"(c) : "l"(a), "l"(b));
}
__device__ __forceinline__ float2 unpack2(ull v) {
    float2 f; asm("mov.b64 {%0, %1}, %2;" : "=f"(f.x), "=f"(f.y) : "l"(v)); return f;
}

// ---------------------------------------------------------------------------
// Attention: one block per (window, head). Gathers qkv rows via order[];
// writes output as bf16 hi/lo planes in point order (proj GEMM A operand).
// ---------------------------------------------------------------------------
#define SM_KS   0
#define SM_S    8448
#define SM_QV   25344
#define SM_RPE  34048
#define SM_INV  34792
#define SM_INT  34920
#define ATTN_SMEM ((34920 + 512) * 4)

__global__ void __launch_bounds__(256, 1) attn_kernel(
    const float* __restrict__ qkv,
    const float* __restrict__ rpe,
    const int*   __restrict__ gcoord,
    const int*   __restrict__ order,
    unsigned short* __restrict__ oh,
    unsigned short* __restrict__ ol)
{
    extern __shared__ float sm[];
    float* ksT  = sm + SM_KS;
    float* S    = sm + SM_S;
    float* qvT  = sm + SM_QV;
    float* rpes = sm + SM_RPE;
    float* invs = sm + SM_INV;
    int* ords = (int*)(sm + SM_INT);
    int* gx = ords + 128;
    int* gy = gx + 128;
    int* gz = gy + 128;

    const int tid  = threadIdx.x;
    const int w    = blockIdx.x >> 3;
    const int h    = blockIdx.x & 7;
    const int lane = tid & 31;
    const int wp   = tid >> 5;

    if (tid < 128) ords[tid] = order[(w << 7) + tid];
    for (int i = tid; i < RPE_ROWS * 8; i += 256) rpes[i] = rpe[i];
    __syncthreads();

    if (tid < 128) {
        int o = ords[tid];
        gx[tid] = gcoord[3 * o];
        gy[tid] = gcoord[3 * o + 1];
        gz[tid] = gcoord[3 * o + 2];
    }

    // ---- gather q (pre-scaled) and k, transposed to [d][p] ----
#pragma unroll
    for (int r = 0; r < 8; r++) {
        int sub = (r << 5) + lane;
        int p   = (wp << 4) + (sub & 15);
        int dg  = (sub >> 4) << 2;
        const float* src = qkv + (size_t)ords[p] * 1536 + h * 64 + dg;
        float4 qv = *(const float4*)src;
        float4 kv = *(const float4*)(src + 512);
        int rb = dg * 132 + p;
        qvT[rb]       = qv.x * SCALEQ;
        qvT[rb + 132] = qv.y * SCALEQ;
        qvT[rb + 264] = qv.z * SCALEQ;
        qvT[rb + 396] = qv.w * SCALEQ;
        ksT[rb]       = kv.x;
        ksT[rb + 132] = kv.y;
        ksT[rb + 264] = kv.z;
        ksT[rb + 396] = kv.w;
    }
    __syncthreads();

    const int ty = tid >> 4, tx = tid & 15;

    // ---- phase 1: S = (q*scale) @ k^T ----
    {
        ull acc[8][4];
#pragma unroll
        for (int i = 0; i < 8; i++)
#pragma unroll
            for (int j = 0; j < 4; j++) acc[i][j] = 0ull;

#pragma unroll 4
        for (int kk = 0; kk < 64; kk++) {
            const float* qrow = qvT + kk * 132;
            const float* krow = ksT + kk * 132;
            float4 af0 = *(const float4*)(qrow + (ty << 2));
            float4 af1 = *(const float4*)(qrow + 64 + (ty << 2));
            const ull* bp0 = (const ull*)(krow + (tx << 2));
            const ull* bp1 = (const ull*)(krow + 64 + (tx << 2));
            ull bb0 = bp0[0], bb1 = bp0[1], bb2 = bp1[0], bb3 = bp1[1];
            float aa[8] = {af0.x, af0.y, af0.z, af0.w,
                           af1.x, af1.y, af1.z, af1.w};
#pragma unroll
            for (int i = 0; i < 8; i++) {
                ull ai = pack2(aa[i]);
                ffma2(acc[i][0], ai, bb0);
                ffma2(acc[i][1], ai, bb1);
                ffma2(acc[i][2], ai, bb2);
                ffma2(acc[i][3], ai, bb3);
            }
        }
#pragma unroll
        for (int i = 0; i < 8; i++) {
            int rr = (i < 4) ? ((ty << 2) + i) : (64 + (ty << 2) + i - 4);
            float* srow = S + rr * 132;
            float2 v;
            v = unpack2(acc[i][0]); *(float2*)(srow + (tx << 2))          = v;
            v = unpack2(acc[i][1]); *(float2*)(srow + (tx << 2) + 2)      = v;
            v = unpack2(acc[i][2]); *(float2*)(srow + 64 + (tx << 2))     = v;
            v = unpack2(acc[i][3]); *(float2*)(srow + 64 + (tx << 2) + 2) = v;
        }
    }
    __syncthreads();

    // ---- gather v into qvT region as vs[128][68] ----
#pragma unroll
    for (int r = 0; r < 8; r++) {
        int sub = (r << 5) + lane;
        int p   = (wp << 4) + (sub & 15);
        int dg  = (sub >> 4) << 2;
        float4 vv = *(const float4*)(qkv + (size_t)ords[p] * 1536 + h * 64 + 1024 + dg);
        *(float4*)&qvT[p * 68 + dg] = vv;
    }

    // ---- softmax with RPE bias: 2 threads per row ----
    {
        const int p  = tid >> 1;
        const int hf = tid & 1;
        const int gpx = gx[p], gpy = gy[p], gpz = gz[p];
        float* srow = S + p * 132 + (hf << 6);
        const int cb = hf << 6;
        float mx = -1e30f;
#pragma unroll 8
        for (int c64 = 0; c64 < 64; c64++) {
            int c = cb + c64;
            int i0 = min(max(gpx - gx[c], -POSBND), POSBND) + POSBND;
            int i1 = min(max(gpy - gy[c], -POSBND), POSBND) + POSBND + 31;
            int i2 = min(max(gpz - gz[c], -POSBND), POSBND) + POSBND + 62;
            float b = rpes[i0 * 8 + h] + rpes[i1 * 8 + h] + rpes[i2 * 8 + h];
            float s = srow[c64] + b;
            srow[c64] = s;
            mx = fmaxf(mx, s);
        }
        mx = fmaxf(mx, __shfl_xor_sync(0xffffffffu, mx, 1));
        float sum = 0.f;
#pragma unroll 8
        for (int c64 = 0; c64 < 64; c64++) {
            float e = __expf(srow[c64] - mx);
            srow[c64] = e;
            sum += e;
        }
        sum += __shfl_xor_sync(0xffffffffu, sum, 1);
        if (hf == 0) invs[p] = 1.0f / sum;
    }
    __syncthreads();

    // ---- phase 2: O = S_exp @ V, scale, split to bf16 hi/lo planes ----
    {
        ull acc2[8][2];
        int rof[8];
#pragma unroll
        for (int i = 0; i < 8; i++) {
            acc2[i][0] = 0ull; acc2[i][1] = 0ull;
            rof[i] = ((i < 4) ? ((ty << 2) + i) : (64 + (ty << 2) + i - 4)) * 132;
        }
#pragma unroll 2
        for (int q4 = 0; q4 < 128; q4 += 4) {
            ull bv[4][2];
#pragma unroll
            for (int j = 0; j < 4; j++) {
                float4 b4 = *(const float4*)(qvT + (q4 + j) * 68 + (tx << 2));
                bv[j][0] = packxy(b4.x, b4.y);
                bv[j][1] = packxy(b4.z, b4.w);
            }
#pragma unroll
            for (int i = 0; i < 8; i++) {
                float4 sv = *(const float4*)(S + rof[i] + q4);
                ull a0 = pack2(sv.x), a1 = pack2(sv.y);
                ull a2 = pack2(sv.z), a3 = pack2(sv.w);
                ffma2(acc2[i][0], a0, bv[0][0]); ffma2(acc2[i][1], a0, bv[0][1]);
                ffma2(acc2[i][0], a1, bv[1][0]); ffma2(acc2[i][1], a1, bv[1][1]);
                ffma2(acc2[i][0], a2, bv[2][0]); ffma2(acc2[i][1], a2, bv[2][1]);
                ffma2(acc2[i][0], a3, bv[3][0]); ffma2(acc2[i][1], a3, bv[3][1]);
            }
        }
#pragma unroll
        for (int i = 0; i < 8; i++) {
            int rr = (i < 4) ? ((ty << 2) + i) : (64 + (ty << 2) + i - 4);
            float iv = invs[rr];
            float2 v0 = unpack2(acc2[i][0]);
            float2 v1 = unpack2(acc2[i][1]);
            float o0 = v0.x * iv, o1 = v0.y * iv, o2 = v1.x * iv, o3 = v1.y * iv;
            size_t off = (size_t)ords[rr] * 512 + (h << 6) + (tx << 2);
            __nv_bfloat16 h0 = __float2bfloat16_rn(o0), h1 = __float2bfloat16_rn(o1),
                          h2 = __float2bfloat16_rn(o2), h3 = __float2bfloat16_rn(o3);
            *(ushort4*)(oh + off) = make_ushort4(
                __bfloat16_as_ushort(h0), __bfloat16_as_ushort(h1),
                __bfloat16_as_ushort(h2), __bfloat16_as_ushort(h3));
            __nv_bfloat16 l0 = __float2bfloat16_rn(o0 - __bfloat162float(h0));
            __nv_bfloat16 l1 = __float2bfloat16_rn(o1 - __bfloat162float(h1));
            __nv_bfloat16 l2 = __float2bfloat16_rn(o2 - __bfloat162float(h2));
            __nv_bfloat16 l3 = __float2bfloat16_rn(o3 - __bfloat162float(h3));
            *(ushort4*)(ol + off) = make_ushort4(
                __bfloat16_as_ushort(l0), __bfloat16_as_ushort(l1),
                __bfloat16_as_ushort(l2), __bfloat16_as_ushort(l3));
        }
    }
}

// ---------------------------------------------------------------------------
extern "C" void kernel_launch(void* const* d_in, const int* in_sizes, int n_in,
                              void* d_out, int out_size)
{
    const float* feat   = (const float*)d_in[0];
    const float* w_qkv  = (const float*)d_in[1];
    const float* b_qkv  = (const float*)d_in[2];
    const float* w_proj = (const float*)d_in[3];
    const float* b_proj = (const float*)d_in[4];
    const float* rpe    = (const float*)d_in[5];
    const int*   gcoord = (const int*)d_in[6];
    const int*   order  = (const int*)d_in[7];
    float* out = (float*)d_out;

    void *pqkv, *pfh, *pfl, *pah, *pal, *pwqh, *pwql, *pwph, *pwpl;
    cudaGetSymbolAddress(&pqkv, g_qkv);
    cudaGetSymbolAddress(&pfh, g_fh);   cudaGetSymbolAddress(&pfl, g_fl);
    cudaGetSymbolAddress(&pah, g_ah);   cudaGetSymbolAddress(&pal, g_al);
    cudaGetSymbolAddress(&pwqh, g_wqh); cudaGetSymbolAddress(&pwql, g_wql);
    cudaGetSymbolAddress(&pwph, g_wph); cudaGetSymbolAddress(&pwpl, g_wpl);

    cudaFuncSetAttribute(attn_kernel,
                         cudaFuncAttributeMaxDynamicSharedMemorySize, ATTN_SMEM);
    cudaFuncSetAttribute(gemm_bf16x3,
                         cudaFuncAttributeMaxDynamicSharedMemorySize, GSM_TOTAL);

    // 1) split fp32 operands into bf16 hi/lo planes
    split_kernel<<<32768, 256>>>(feat,   (unsigned short*)pfh,  (unsigned short*)pfl);
    split_kernel<<<768,   256>>>(w_qkv,  (unsigned short*)pwqh, (unsigned short*)pwql);
    split_kernel<<<256,   256>>>(w_proj, (unsigned short*)pwph, (unsigned short*)pwpl);

    // 2) dense QKV projection (mma.sync bf16x3) -> g_qkv [N][1536] (point order)
    gemm_bf16x3<<<dim3(12, 512), 256, GSM_TOTAL>>>(
        (const __nv_bfloat16*)pfh,  (const __nv_bfloat16*)pfl,
        (const __nv_bfloat16*)pwqh, (const __nv_bfloat16*)pwql,
        b_qkv, (float*)pqkv, 1536);

    // 3) windowed attention (gathers via order) -> bf16 hi/lo planes (point order)
    attn_kernel<<<NWIN * NH, 256, ATTN_SMEM>>>(
        (const float*)pqkv, rpe, gcoord, order,
        (unsigned short*)pah, (unsigned short*)pal);

    // 4) output projection (mma.sync bf16x3) -> d_out
    gemm_bf16x3<<<dim3(4, 512), 256, GSM_TOTAL>>>(
        (const __nv_bfloat16*)pah,  (const __nv_bfloat16*)pal,
        (const __nv_bfloat16*)pwph, (const __nv_bfloat16*)pwpl,
        b_proj, out, 512);
}

// round 8
// speedup vs baseline: 1.6907x; 1.0656x over previous
#include <cuda_runtime.h>
#include <cuda_bf16.h>
#include <cstdint>

typedef unsigned long long ull;
typedef unsigned int u32;

#define NPTS    65536
#define NWIN    512
#define NH      8
#define POSBND  15
#define RPE_ROWS 93
#define SCALEQ  0.125f

// ---------------- device scratch (no allocation APIs allowed) ----------------
__device__ float          g_qkv[100663296];   // [N][1536] fp32, point order
__device__ unsigned short g_fh[33554432];     // feat hi/lo bf16 planes [N][512]
__device__ unsigned short g_fl[33554432];
__device__ unsigned short g_ah[33554432];     // attn out hi/lo planes [N][512]
__device__ unsigned short g_al[33554432];
__device__ unsigned short g_wqh[786432];      // w_qkv planes [1536][512]
__device__ unsigned short g_wql[786432];
__device__ unsigned short g_wph[262144];      // w_proj planes [512][512]
__device__ unsigned short g_wpl[262144];

// ---------------- PTX helpers (all sm_80-era, compute_100-safe) ----------------
__device__ __forceinline__ u32 s2u(const void* p) {
    u32 a; asm("{ .reg .u64 t; cvta.to.shared.u64 t, %1; cvt.u32.u64 %0, t; }"
               : "=r"(a) : "l"(p)); return a;
}
__device__ __forceinline__ void cp16(u32 dst, const void* src) {
    asm volatile("cp.async.cg.shared.global [%0], [%1], 16;" :: "r"(dst), "l"(src) : "memory");
}
__device__ __forceinline__ void cp_commit() {
    asm volatile("cp.async.commit_group;" ::: "memory");
}
__device__ __forceinline__ void ldsm4(u32* r, u32 addr) {
    asm volatile("ldmatrix.sync.aligned.m8n8.x4.shared.b16 {%0,%1,%2,%3}, [%4];"
        : "=r"(r[0]), "=r"(r[1]), "=r"(r[2]), "=r"(r[3]) : "r"(addr));
}
__device__ __forceinline__ void ldsm2(u32* r, u32 addr) {
    asm volatile("ldmatrix.sync.aligned.m8n8.x2.shared.b16 {%0,%1}, [%2];"
        : "=r"(r[0]), "=r"(r[1]) : "r"(addr));
}
__device__ __forceinline__ void mma16816(float* c, const u32* a, const u32* b) {
    asm volatile("mma.sync.aligned.m16n8k16.row.col.f32.bf16.bf16.f32 "
        "{%0,%1,%2,%3}, {%4,%5,%6,%7}, {%8,%9}, {%0,%1,%2,%3};"
        : "+f"(c[0]), "+f"(c[1]), "+f"(c[2]), "+f"(c[3])
        : "r"(a[0]), "r"(a[1]), "r"(a[2]), "r"(a[3]), "r"(b[0]), "r"(b[1]));
}
__device__ __forceinline__ u32 bfpack(float x, float y) {
    unsigned short a = __bfloat16_as_ushort(__float2bfloat16_rn(x));
    unsigned short b = __bfloat16_as_ushort(__float2bfloat16_rn(y));
    return (u32)a | ((u32)b << 16);
}

// ---------------- fp32 -> bf16 hi/lo split (elementwise) ----------------
__global__ void __launch_bounds__(256) split_kernel(
    const float* __restrict__ x,
    unsigned short* __restrict__ hi, unsigned short* __restrict__ lo)
{
    int i = (blockIdx.x * 256 + threadIdx.x) * 4;
    float4 v = *(const float4*)(x + i);
    __nv_bfloat16 h0 = __float2bfloat16_rn(v.x), h1 = __float2bfloat16_rn(v.y),
                  h2 = __float2bfloat16_rn(v.z), h3 = __float2bfloat16_rn(v.w);
    *(ushort4*)(hi + i) = make_ushort4(
        __bfloat16_as_ushort(h0), __bfloat16_as_ushort(h1),
        __bfloat16_as_ushort(h2), __bfloat16_as_ushort(h3));
    __nv_bfloat16 l0 = __float2bfloat16_rn(v.x - __bfloat162float(h0));
    __nv_bfloat16 l1 = __float2bfloat16_rn(v.y - __bfloat162float(h1));
    __nv_bfloat16 l2 = __float2bfloat16_rn(v.z - __bfloat162float(h2));
    __nv_bfloat16 l3 = __float2bfloat16_rn(v.w - __bfloat162float(h3));
    *(ushort4*)(lo + i) = make_ushort4(
        __bfloat16_as_ushort(l0), __bfloat16_as_ushort(l1),
        __bfloat16_as_ushort(l2), __bfloat16_as_ushort(l3));
}

// ---------------------------------------------------------------------------
// mma.sync bf16x3 GEMM (unchanged from round 6 — proven)
// ---------------------------------------------------------------------------
#define PLANE_B  10240
#define STAGE_B  40960
#define GSM_TOTAL (2 * STAGE_B)

__global__ void __launch_bounds__(256, 2) gemm_bf16x3(
    const __nv_bfloat16* __restrict__ Ah, const __nv_bfloat16* __restrict__ Al,
    const __nv_bfloat16* __restrict__ Bh, const __nv_bfloat16* __restrict__ Bl,
    const float* __restrict__ bias, float* __restrict__ C, int ldc)
{
    extern __shared__ char smem[];
    const u32 sb = s2u(smem);

    const int tid  = threadIdx.x;
    const int lane = tid & 31;
    const int wid  = tid >> 5;
    const int wm   = wid >> 2;
    const int wn   = wid & 3;
    const int rowBlk = blockIdx.y << 7, colBlk = blockIdx.x << 7;

    const int crow = tid >> 1;
    const int u0   = (tid & 1) * 2;
    const u32 dst_row = (u32)(crow * 80);
    const __nv_bfloat16* pa_h = Ah + (size_t)(rowBlk + crow) * 512 + u0 * 8;
    const __nv_bfloat16* pa_l = Al + (size_t)(rowBlk + crow) * 512 + u0 * 8;
    const __nv_bfloat16* pb_h = Bh + (size_t)(colBlk + crow) * 512 + u0 * 8;
    const __nv_bfloat16* pb_l = Bl + (size_t)(colBlk + crow) * 512 + u0 * 8;

    auto fill = [&](int st, int c) {
        u32 base = sb + st * STAGE_B + dst_row + u0 * 16;
        const __nv_bfloat16* s0 = pa_h + c * 32;
        const __nv_bfloat16* s1 = pa_l + c * 32;
        const __nv_bfloat16* s2 = pb_h + c * 32;
        const __nv_bfloat16* s3 = pb_l + c * 32;
        cp16(base,                  s0); cp16(base + 16,                  s0 + 8);
        cp16(base + PLANE_B,        s1); cp16(base + PLANE_B + 16,        s1 + 8);
        cp16(base + 2 * PLANE_B,    s2); cp16(base + 2 * PLANE_B + 16,    s2 + 8);
        cp16(base + 3 * PLANE_B,    s3); cp16(base + 3 * PLANE_B + 16,    s3 + 8);
        cp_commit();
    };

    float acc[4][4][4];
#pragma unroll
    for (int mi = 0; mi < 4; mi++)
#pragma unroll
        for (int ni = 0; ni < 4; ni++)
#pragma unroll
            for (int j = 0; j < 4; j++) acc[mi][ni][j] = 0.f;

    const int a_row = (wm << 6) + ((lane >> 3) & 1) * 8 + (lane & 7);
    const int a_k8  = (lane >> 4) * 8;
    const int b_row = (wn << 5) + (lane & 7);
    const int b_k8  = ((lane >> 3) & 1) * 8;

    fill(0, 0);
    fill(1, 1);

    const int KI = 16;
#pragma unroll 1
    for (int c = 0; c < KI; c++) {
        const int buf = c & 1;
        if (c + 1 < KI) asm volatile("cp.async.wait_group 1;" ::: "memory");
        else            asm volatile("cp.async.wait_group 0;" ::: "memory");
        __syncthreads();

        const u32 As_h = sb + buf * STAGE_B;
        const u32 As_l = As_h + PLANE_B;
        const u32 Bs_h = As_h + 2 * PLANE_B;
        const u32 Bs_l = As_h + 3 * PLANE_B;

#pragma unroll
        for (int ks = 0; ks < 2; ks++) {
            const u32 a_off = (u32)(a_row * 80 + (ks * 16 + a_k8) * 2);
            const u32 b_off = (u32)(b_row * 80 + (ks * 16 + b_k8) * 2);
            u32 bh[4][2], bl[4][2];
#pragma unroll
            for (int ni = 0; ni < 4; ni++) {
                ldsm2(bh[ni], Bs_h + b_off + ni * 8 * 80);
                ldsm2(bl[ni], Bs_l + b_off + ni * 8 * 80);
            }
#pragma unroll
            for (int mi = 0; mi < 4; mi++) {
                u32 ah[4], al[4];
                ldsm4(ah, As_h + a_off + mi * 16 * 80);
                ldsm4(al, As_l + a_off + mi * 16 * 80);
#pragma unroll
                for (int ni = 0; ni < 4; ni++) {
                    mma16816(acc[mi][ni], ah, bh[ni]);
                    mma16816(acc[mi][ni], ah, bl[ni]);
                    mma16816(acc[mi][ni], al, bh[ni]);
                }
            }
        }
        __syncthreads();
        if (c + 2 < KI) fill(buf, c + 2);
    }

    const int mrow = rowBlk + (wm << 6) + (lane >> 2);
    const int ncol = colBlk + (wn << 5) + (lane & 3) * 2;
#pragma unroll
    for (int ni = 0; ni < 4; ni++) {
        const int n0 = ncol + ni * 8;
        const float b0 = bias[n0], b1 = bias[n0 + 1];
#pragma unroll
        for (int mi = 0; mi < 4; mi++) {
            float* d0 = C + (size_t)(mrow + mi * 16) * ldc + n0;
            float* d1 = d0 + 8 * ldc;
            float2 v0 = make_float2(acc[mi][ni][0] + b0, acc[mi][ni][1] + b1);
            float2 v1 = make_float2(acc[mi][ni][2] + b0, acc[mi][ni][3] + b1);
            *(float2*)d0 = v0;
            *(float2*)d1 = v1;
        }
    }
}

// ---------------------------------------------------------------------------
// Attention with tensor-core phases. One block per (window, head), 256 threads.
// smem byte offsets:
//   Qh [128][72]h @0, Ql @18432, Kh @36864, Kl @55296   (pitch 144B)
//   S  fp32 [128][132] @73728 (pitch 528B)
//   VTh [64][136]h @141312, VTl @158720                  (pitch 272B, [d][q])
//   misc @176128: rpes f[744], invs f[128], ords i[128], gx/gy/gz i[128]
//   Ph [128][136]h @0 (alias Q/K), Pl @34816             (pitch 272B)
// ---------------------------------------------------------------------------
#define AQ_H   0
#define AQ_L   18432
#define AK_H   36864
#define AK_L   55296
#define AS     73728
#define AVT_H  141312
#define AVT_L  158720
#define AMISC  176128
#define AP_H   0
#define AP_L   34816
#define ATTN_SMEM 181664

__global__ void __launch_bounds__(256, 1) attn_kernel(
    const float* __restrict__ qkv,
    const float* __restrict__ rpe,
    const int*   __restrict__ gcoord,
    const int*   __restrict__ order,
    unsigned short* __restrict__ oh,
    unsigned short* __restrict__ ol)
{
    extern __shared__ char smb[];
    const u32 sb = s2u(smb);
    float* S    = (float*)(smb + AS);
    float* rpes = (float*)(smb + AMISC);
    float* invs = (float*)(smb + AMISC + 2976);
    int* ords = (int*)(smb + AMISC + 3488);
    int* gx   = ords + 128;
    int* gy   = gx + 128;
    int* gz   = gy + 128;

    const int tid  = threadIdx.x;
    const int w    = blockIdx.x >> 3;
    const int h    = blockIdx.x & 7;
    const int lane = tid & 31;
    const int wid  = tid >> 5;

    if (tid < 128) ords[tid] = order[(w << 7) + tid];
    for (int i = tid; i < RPE_ROWS * 8; i += 256) rpes[i] = rpe[i];
    __syncthreads();

    if (tid < 128) {
        int o = ords[tid];
        gx[tid] = gcoord[3 * o];
        gy[tid] = gcoord[3 * o + 1];
        gz[tid] = gcoord[3 * o + 2];
    }

    // ---- gather q (pre-scaled) + k, split to bf16 hi/lo planes [p][d] ----
    {
        const int wp = wid;
#pragma unroll
        for (int r = 0; r < 8; r++) {
            int sub = (r << 5) + lane;              // 0..255 within warp block
            int p   = (wp << 4) + (sub & 15);
            int dg  = (sub >> 4) << 2;              // 0,4,...,60
            const float* src = qkv + (size_t)ords[p] * 1536 + h * 64 + dg;
            float4 qv = *(const float4*)src;
            qv.x *= SCALEQ; qv.y *= SCALEQ; qv.z *= SCALEQ; qv.w *= SCALEQ;
            float4 kv = *(const float4*)(src + 512);
            u32 off = (u32)(p * 144 + dg * 2);
            // hi planes
            uint2 qh = make_uint2(bfpack(qv.x, qv.y), bfpack(qv.z, qv.w));
            uint2 kh = make_uint2(bfpack(kv.x, kv.y), bfpack(kv.z, kv.w));
            *(uint2*)(smb + AQ_H + off) = qh;
            *(uint2*)(smb + AK_H + off) = kh;
            // lo planes (residuals)
            float qr0 = qv.x - __bfloat162float(__ushort_as_bfloat16((unsigned short)(qh.x & 0xffff)));
            float qr1 = qv.y - __bfloat162float(__ushort_as_bfloat16((unsigned short)(qh.x >> 16)));
            float qr2 = qv.z - __bfloat162float(__ushort_as_bfloat16((unsigned short)(qh.y & 0xffff)));
            float qr3 = qv.w - __bfloat162float(__ushort_as_bfloat16((unsigned short)(qh.y >> 16)));
            float kr0 = kv.x - __bfloat162float(__ushort_as_bfloat16((unsigned short)(kh.x & 0xffff)));
            float kr1 = kv.y - __bfloat162float(__ushort_as_bfloat16((unsigned short)(kh.x >> 16)));
            float kr2 = kv.z - __bfloat162float(__ushort_as_bfloat16((unsigned short)(kh.y & 0xffff)));
            float kr3 = kv.w - __bfloat162float(__ushort_as_bfloat16((unsigned short)(kh.y >> 16)));
            *(uint2*)(smb + AQ_L + off) = make_uint2(bfpack(qr0, qr1), bfpack(qr2, qr3));
            *(uint2*)(smb + AK_L + off) = make_uint2(bfpack(kr0, kr1), bfpack(kr2, kr3));
        }
    }
    __syncthreads();

    // ---- phase 1: S = q @ k^T via mma (2m x 4n warps, 64x32 each) ----
    {
        const int wm = wid >> 2, wn = wid & 3;
        float acc[4][4][4];
#pragma unroll
        for (int mi = 0; mi < 4; mi++)
#pragma unroll
            for (int ni = 0; ni < 4; ni++)
#pragma unroll
                for (int j = 0; j < 4; j++) acc[mi][ni][j] = 0.f;

        const int a_row = (wm << 6) + ((lane >> 3) & 1) * 8 + (lane & 7);
        const int a_k8  = (lane >> 4) * 8;
        const int b_row = (wn << 5) + (lane & 7);
        const int b_k8  = ((lane >> 3) & 1) * 8;

#pragma unroll
        for (int ks = 0; ks < 4; ks++) {
            const u32 a_off = (u32)(a_row * 144 + (ks * 16 + a_k8) * 2);
            const u32 b_off = (u32)(b_row * 144 + (ks * 16 + b_k8) * 2);
            u32 bh[4][2], bl[4][2];
#pragma unroll
            for (int ni = 0; ni < 4; ni++) {
                ldsm2(bh[ni], sb + AK_H + b_off + ni * 8 * 144);
                ldsm2(bl[ni], sb + AK_L + b_off + ni * 8 * 144);
            }
#pragma unroll
            for (int mi = 0; mi < 4; mi++) {
                u32 ah[4], al[4];
                ldsm4(ah, sb + AQ_H + a_off + mi * 16 * 144);
                ldsm4(al, sb + AQ_L + a_off + mi * 16 * 144);
#pragma unroll
                for (int ni = 0; ni < 4; ni++) {
                    mma16816(acc[mi][ni], ah, bh[ni]);
                    mma16816(acc[mi][ni], ah, bl[ni]);
                    mma16816(acc[mi][ni], al, bh[ni]);
                }
            }
        }
        // write S (fp32)
#pragma unroll
        for (int mi = 0; mi < 4; mi++) {
            const int r0 = (wm << 6) + mi * 16 + (lane >> 2);
#pragma unroll
            for (int ni = 0; ni < 4; ni++) {
                const int c0 = (wn << 5) + ni * 8 + (lane & 3) * 2;
                *(float2*)(S + r0 * 132 + c0)       = make_float2(acc[mi][ni][0], acc[mi][ni][1]);
                *(float2*)(S + (r0 + 8) * 132 + c0) = make_float2(acc[mi][ni][2], acc[mi][ni][3]);
            }
        }
    }
    __syncthreads();

    // ---- gather v transposed into VT planes [d][q] (hi/lo) ----
    {
        const int wp = wid;
#pragma unroll
        for (int r = 0; r < 8; r++) {
            int sub = (r << 5) + lane;
            int p   = (wp << 4) + (sub & 15);
            int dg  = (sub >> 4) << 2;
            float4 vv = *(const float4*)(qkv + (size_t)ords[p] * 1536 + h * 64 + 1024 + dg);
            float vs[4] = {vv.x, vv.y, vv.z, vv.w};
#pragma unroll
            for (int j = 0; j < 4; j++) {
                __nv_bfloat16 hb = __float2bfloat16_rn(vs[j]);
                __nv_bfloat16 lb = __float2bfloat16_rn(vs[j] - __bfloat162float(hb));
                u32 off = (u32)((dg + j) * 272 + p * 2);
                *(unsigned short*)(smb + AVT_H + off) = __bfloat16_as_ushort(hb);
                *(unsigned short*)(smb + AVT_L + off) = __bfloat16_as_ushort(lb);
            }
        }
    }

    // ---- softmax with RPE bias: 2 threads per row ----
    {
        const int p  = tid >> 1;
        const int hf = tid & 1;
        const int gpx = gx[p], gpy = gy[p], gpz = gz[p];
        float* srow = S + p * 132 + (hf << 6);
        const int cb = hf << 6;
        float mx = -1e30f;
#pragma unroll 8
        for (int c64 = 0; c64 < 64; c64++) {
            int c = cb + c64;
            int i0 = min(max(gpx - gx[c], -POSBND), POSBND) + POSBND;
            int i1 = min(max(gpy - gy[c], -POSBND), POSBND) + POSBND + 31;
            int i2 = min(max(gpz - gz[c], -POSBND), POSBND) + POSBND + 62;
            float b = rpes[i0 * 8 + h] + rpes[i1 * 8 + h] + rpes[i2 * 8 + h];
            float s = srow[c64] + b;
            srow[c64] = s;
            mx = fmaxf(mx, s);
        }
        mx = fmaxf(mx, __shfl_xor_sync(0xffffffffu, mx, 1));
        float sum = 0.f;
#pragma unroll 8
        for (int c64 = 0; c64 < 64; c64++) {
            float e = __expf(srow[c64] - mx);
            srow[c64] = e;
            sum += e;
        }
        sum += __shfl_xor_sync(0xffffffffu, sum, 1);
        if (hf == 0) invs[p] = 1.0f / sum;
    }
    __syncthreads();

    // ---- convert P (=exp, unnormalized) to bf16 hi/lo planes (alias Q/K) ----
    {
        const int p  = tid >> 1;
        const int q0 = (tid & 1) << 6;
        const float* srow = S + p * 132 + q0;
        u32 dst = (u32)(p * 272 + q0 * 2);
#pragma unroll 4
        for (int j = 0; j < 64; j += 4) {
            float4 v = *(const float4*)(srow + j);
            u32 h0 = bfpack(v.x, v.y), h1 = bfpack(v.z, v.w);
            float r0 = v.x - __bfloat162float(__ushort_as_bfloat16((unsigned short)(h0 & 0xffff)));
            float r1 = v.y - __bfloat162float(__ushort_as_bfloat16((unsigned short)(h0 >> 16)));
            float r2 = v.z - __bfloat162float(__ushort_as_bfloat16((unsigned short)(h1 & 0xffff)));
            float r3 = v.w - __bfloat162float(__ushort_as_bfloat16((unsigned short)(h1 >> 16)));
            *(uint2*)(smb + AP_H + dst + j * 2) = make_uint2(h0, h1);
            *(uint2*)(smb + AP_L + dst + j * 2) = make_uint2(bfpack(r0, r1), bfpack(r2, r3));
        }
    }
    __syncthreads();

    // ---- phase 2: O = P @ V via mma (4m x 2n warps, 32x32 each) ----
    {
        const int wm2 = wid >> 1, wn2 = wid & 1;
        float acc[2][4][4];
#pragma unroll
        for (int mi = 0; mi < 2; mi++)
#pragma unroll
            for (int ni = 0; ni < 4; ni++)
#pragma unroll
                for (int j = 0; j < 4; j++) acc[mi][ni][j] = 0.f;

        const int a_row = (wm2 << 5) + ((lane >> 3) & 1) * 8 + (lane & 7);
        const int a_k8  = (lane >> 4) * 8;
        const int b_row = (wn2 << 5) + (lane & 7);
        const int b_k8  = ((lane >> 3) & 1) * 8;

#pragma unroll
        for (int ks = 0; ks < 8; ks++) {
            const u32 a_off = (u32)(a_row * 272 + (ks * 16 + a_k8) * 2);
            const u32 b_off = (u32)(b_row * 272 + (ks * 16 + b_k8) * 2);
            u32 bh[4][2], bl[4][2];
#pragma unroll
            for (int ni = 0; ni < 4; ni++) {
                ldsm2(bh[ni], sb + AVT_H + b_off + ni * 8 * 272);
                ldsm2(bl[ni], sb + AVT_L + b_off + ni * 8 * 272);
            }
#pragma unroll
            for (int mi = 0; mi < 2; mi++) {
                u32 ah[4], al[4];
                ldsm4(ah, sb + AP_H + a_off + mi * 16 * 272);
                ldsm4(al, sb + AP_L + a_off + mi * 16 * 272);
#pragma unroll
                for (int ni = 0; ni < 4; ni++) {
                    mma16816(acc[mi][ni], ah, bh[ni]);
                    mma16816(acc[mi][ni], ah, bl[ni]);
                    mma16816(acc[mi][ni], al, bh[ni]);
                }
            }
        }
        // epilogue: scale by 1/sum, split to bf16 hi/lo, scatter by ords
#pragma unroll
        for (int mi = 0; mi < 2; mi++) {
            const int p0 = (wm2 << 5) + mi * 16 + (lane >> 2);
            const int p1 = p0 + 8;
            const float iv0 = invs[p0], iv1 = invs[p1];
            const size_t g0 = (size_t)ords[p0] * 512 + (h << 6);
            const size_t g1 = (size_t)ords[p1] * 512 + (h << 6);
#pragma unroll
            for (int ni = 0; ni < 4; ni++) {
                const int d0 = (wn2 << 5) + ni * 8 + (lane & 3) * 2;
                float o00 = acc[mi][ni][0] * iv0, o01 = acc[mi][ni][1] * iv0;
                float o10 = acc[mi][ni][2] * iv1, o11 = acc[mi][ni][3] * iv1;
                __nv_bfloat16 h00 = __float2bfloat16_rn(o00), h01 = __float2bfloat16_rn(o01);
                __nv_bfloat16 h10 = __float2bfloat16_rn(o10), h11 = __float2bfloat16_rn(o11);
                *(ushort2*)(oh + g0 + d0) = make_ushort2(__bfloat16_as_ushort(h00), __bfloat16_as_ushort(h01));
                *(ushort2*)(oh + g1 + d0) = make_ushort2(__bfloat16_as_ushort(h10), __bfloat16_as_ushort(h11));
                __nv_bfloat16 l00 = __float2bfloat16_rn(o00 - __bfloat162float(h00));
                __nv_bfloat16 l01 = __float2bfloat16_rn(o01 - __bfloat162float(h01));
                __nv_bfloat16 l10 = __float2bfloat16_rn(o10 - __bfloat162float(h10));
                __nv_bfloat16 l11 = __float2bfloat16_rn(o11 - __bfloat162float(h11));
                *(ushort2*)(ol + g0 + d0) = make_ushort2(__bfloat16_as_ushort(l00), __bfloat16_as_ushort(l01));
                *(ushort2*)(ol + g1 + d0) = make_ushort2(__bfloat16_as_ushort(l10), __bfloat16_as_ushort(l11));
            }
        }
    }
}

// ---------------------------------------------------------------------------
extern "C" void kernel_launch(void* const* d_in, const int* in_sizes, int n_in,
                              void* d_out, int out_size)
{
    const float* feat   = (const float*)d_in[0];
    const float* w_qkv  = (const float*)d_in[1];
    const float* b_qkv  = (const float*)d_in[2];
    const float* w_proj = (const float*)d_in[3];
    const float* b_proj = (const float*)d_in[4];
    const float* rpe    = (const float*)d_in[5];
    const int*   gcoord = (const int*)d_in[6];
    const int*   order  = (const int*)d_in[7];
    float* out = (float*)d_out;

    void *pqkv, *pfh, *pfl, *pah, *pal, *pwqh, *pwql, *pwph, *pwpl;
    cudaGetSymbolAddress(&pqkv, g_qkv);
    cudaGetSymbolAddress(&pfh, g_fh);   cudaGetSymbolAddress(&pfl, g_fl);
    cudaGetSymbolAddress(&pah, g_ah);   cudaGetSymbolAddress(&pal, g_al);
    cudaGetSymbolAddress(&pwqh, g_wqh); cudaGetSymbolAddress(&pwql, g_wql);
    cudaGetSymbolAddress(&pwph, g_wph); cudaGetSymbolAddress(&pwpl, g_wpl);

    cudaFuncSetAttribute(attn_kernel,
                         cudaFuncAttributeMaxDynamicSharedMemorySize, ATTN_SMEM);
    cudaFuncSetAttribute(gemm_bf16x3,
                         cudaFuncAttributeMaxDynamicSharedMemorySize, GSM_TOTAL);

    // 1) split fp32 operands into bf16 hi/lo planes
    split_kernel<<<32768, 256>>>(feat,   (unsigned short*)pfh,  (unsigned short*)pfl);
    split_kernel<<<768,   256>>>(w_qkv,  (unsigned short*)pwqh, (unsigned short*)pwql);
    split_kernel<<<256,   256>>>(w_proj, (unsigned short*)pwph, (unsigned short*)pwpl);

    // 2) dense QKV projection (mma.sync bf16x3) -> g_qkv [N][1536] (point order)
    gemm_bf16x3<<<dim3(12, 512), 256, GSM_TOTAL>>>(
        (const __nv_bfloat16*)pfh,  (const __nv_bfloat16*)pfl,
        (const __nv_bfloat16*)pwqh, (const __nv_bfloat16*)pwql,
        b_qkv, (float*)pqkv, 1536);

    // 3) windowed attention (tensor-core phases) -> bf16 hi/lo planes
    attn_kernel<<<NWIN * NH, 256, ATTN_SMEM>>>(
        (const float*)pqkv, rpe, gcoord, order,
        (unsigned short*)pah, (unsigned short*)pal);

    // 4) output projection (mma.sync bf16x3) -> d_out
    gemm_bf16x3<<<dim3(4, 512), 256, GSM_TOTAL>>>(
        (const __nv_bfloat16*)pah,  (const __nv_bfloat16*)pal,
        (const __nv_bfloat16*)pwph, (const __nv_bfloat16*)pwpl,
        b_proj, out, 512);
}